// round 1
// baseline (speedup 1.0000x reference)
#include <cuda_runtime.h>
#include <cuda_bf16.h>
#include <stdint.h>

#define N_NODES 100000
#define N_EDGES 1600000
#define D_IN    256
#define D_OUT   128

// ---------------- device scratch (no allocations allowed) ----------------
__device__ float g_support[(size_t)N_NODES * D_OUT];   // X @ W   (51.2 MB)
__device__ int   g_counts[N_NODES];
__device__ int   g_rowptr[N_NODES + 1];
__device__ int   g_cursor[N_NODES];
__device__ int2  g_sorted_cv[N_EDGES];                 // (col, val-bits) sorted by row

#define SCAN_B 1024
#define NSB    ((N_NODES + SCAN_B - 1) / SCAN_B)       // 98
__device__ int   g_blocksums[NSB];

// ---------------- 1) SGEMM: support = X @ W  (fp32, 128x128x16 tiles) ----
#define BM 128
#define BN 128
#define BK 16

__global__ __launch_bounds__(256, 2)
void gemm_kernel(const float* __restrict__ A, const float* __restrict__ W) {
    __shared__ float As[BK][BM];
    __shared__ float Bs[BK][BN];

    const int tid = threadIdx.x;           // 0..255
    const int m0  = blockIdx.x * BM;
    const int tx  = tid & 15;              // 0..15 -> 8 cols each
    const int ty  = tid >> 4;              // 0..15 -> 8 rows each

    float acc[8][8];
#pragma unroll
    for (int i = 0; i < 8; i++)
#pragma unroll
        for (int j = 0; j < 8; j++) acc[i][j] = 0.f;

    for (int k0 = 0; k0 < D_IN; k0 += BK) {
        // load A tile (128x16) transposed into As[k][m]
#pragma unroll
        for (int l = 0; l < 2; l++) {
            int idx = tid + l * 256;       // 0..511
            int ar  = idx >> 2;            // 0..127
            int ac  = (idx & 3) * 4;       // 0,4,8,12
            float4 av = make_float4(0.f, 0.f, 0.f, 0.f);
            int gr = m0 + ar;
            if (gr < N_NODES)
                av = *(const float4*)&A[(size_t)gr * D_IN + k0 + ac];
            As[ac + 0][ar] = av.x;
            As[ac + 1][ar] = av.y;
            As[ac + 2][ar] = av.z;
            As[ac + 3][ar] = av.w;
        }
        // load B tile (16x128) direct
#pragma unroll
        for (int l = 0; l < 2; l++) {
            int idx = tid + l * 256;       // 0..511
            int br  = idx >> 5;            // 0..15
            int bc  = (idx & 31) * 4;      // 0..124
            *(float4*)&Bs[br][bc] = *(const float4*)&W[(size_t)(k0 + br) * D_OUT + bc];
        }
        __syncthreads();

#pragma unroll
        for (int kk = 0; kk < BK; kk++) {
            float a[8], b[8];
            *(float4*)&a[0] = *(const float4*)&As[kk][ty * 8 + 0];
            *(float4*)&a[4] = *(const float4*)&As[kk][ty * 8 + 4];
            *(float4*)&b[0] = *(const float4*)&Bs[kk][tx * 8 + 0];
            *(float4*)&b[4] = *(const float4*)&Bs[kk][tx * 8 + 4];
#pragma unroll
            for (int i = 0; i < 8; i++)
#pragma unroll
                for (int j = 0; j < 8; j++)
                    acc[i][j] += a[i] * b[j];
        }
        __syncthreads();
    }

#pragma unroll
    for (int i = 0; i < 8; i++) {
        int r = m0 + ty * 8 + i;
        if (r < N_NODES) {
            *(float4*)&g_support[(size_t)r * D_OUT + tx * 8 + 0] =
                make_float4(acc[i][0], acc[i][1], acc[i][2], acc[i][3]);
            *(float4*)&g_support[(size_t)r * D_OUT + tx * 8 + 4] =
                make_float4(acc[i][4], acc[i][5], acc[i][6], acc[i][7]);
        }
    }
}

// ---------------- 2) CSR build: histogram -> scan -> scatter -------------
__global__ void zero_counts_kernel() {
    int i = blockIdx.x * blockDim.x + threadIdx.x;
    if (i < N_NODES) g_counts[i] = 0;
}

__global__ void hist_kernel(const int* __restrict__ rows) {
    int e = blockIdx.x * blockDim.x + threadIdx.x;
    if (e < N_EDGES) atomicAdd(&g_counts[rows[e]], 1);
}

__global__ __launch_bounds__(SCAN_B)
void scan1_kernel() {
    __shared__ int sh[SCAN_B];
    int i = blockIdx.x * SCAN_B + threadIdx.x;
    int v = (i < N_NODES) ? g_counts[i] : 0;
    sh[threadIdx.x] = v;
    __syncthreads();
#pragma unroll
    for (int off = 1; off < SCAN_B; off <<= 1) {
        int t = (threadIdx.x >= off) ? sh[threadIdx.x - off] : 0;
        __syncthreads();
        sh[threadIdx.x] += t;
        __syncthreads();
    }
    if (i < N_NODES) g_rowptr[i] = sh[threadIdx.x] - v;   // block-local exclusive
    if (threadIdx.x == SCAN_B - 1) g_blocksums[blockIdx.x] = sh[SCAN_B - 1];
}

__global__ void scan2_kernel() {
    if (threadIdx.x == 0 && blockIdx.x == 0) {
        int acc = 0;
        for (int b = 0; b < NSB; b++) {
            int t = g_blocksums[b];
            g_blocksums[b] = acc;
            acc += t;
        }
    }
}

__global__ void scan3_kernel() {
    int i = blockIdx.x * blockDim.x + threadIdx.x;
    if (i < N_NODES) {
        int v = g_rowptr[i] + g_blocksums[i / SCAN_B];
        g_rowptr[i] = v;
        g_cursor[i] = v;
    }
    if (i == 0) g_rowptr[N_NODES] = N_EDGES;
}

__global__ void scatter_kernel(const int* __restrict__ rows,
                               const int* __restrict__ cols,
                               const float* __restrict__ vals) {
    int e = blockIdx.x * blockDim.x + threadIdx.x;
    if (e >= N_EDGES) return;
    int r = rows[e];
    int p = atomicAdd(&g_cursor[r], 1);
    g_sorted_cv[p] = make_int2(cols[e], __float_as_int(vals[e]));
}

// ---------------- 3) Aggregate: one warp per row, no atomics -------------
__global__ __launch_bounds__(256)
void aggregate_kernel(const float* __restrict__ bias, float* __restrict__ out) {
    int w    = (blockIdx.x * blockDim.x + threadIdx.x) >> 5;   // row id
    int lane = threadIdx.x & 31;
    if (w >= N_NODES) return;

    int s = g_rowptr[w];
    int e = g_rowptr[w + 1];

    float4 acc = make_float4(0.f, 0.f, 0.f, 0.f);
    int j = s;
    // unroll-by-2 for memory-level parallelism on the L2 gathers
    for (; j + 1 < e; j += 2) {
        int2 cv0 = g_sorted_cv[j];
        int2 cv1 = g_sorted_cv[j + 1];
        float v0 = __int_as_float(cv0.y);
        float v1 = __int_as_float(cv1.y);
        float4 s0 = *(const float4*)&g_support[(size_t)cv0.x * D_OUT + lane * 4];
        float4 s1 = *(const float4*)&g_support[(size_t)cv1.x * D_OUT + lane * 4];
        acc.x += v0 * s0.x; acc.y += v0 * s0.y; acc.z += v0 * s0.z; acc.w += v0 * s0.w;
        acc.x += v1 * s1.x; acc.y += v1 * s1.y; acc.z += v1 * s1.z; acc.w += v1 * s1.w;
    }
    if (j < e) {
        int2 cv = g_sorted_cv[j];
        float v = __int_as_float(cv.y);
        float4 s0 = *(const float4*)&g_support[(size_t)cv.x * D_OUT + lane * 4];
        acc.x += v * s0.x; acc.y += v * s0.y; acc.z += v * s0.z; acc.w += v * s0.w;
    }

    float4 b = ((const float4*)bias)[lane];
    acc.x += b.x; acc.y += b.y; acc.z += b.z; acc.w += b.w;
    *(float4*)&out[(size_t)w * D_OUT + lane * 4] = acc;
}

// ---------------- launch ------------------------------------------------
extern "C" void kernel_launch(void* const* d_in, const int* in_sizes, int n_in,
                              void* d_out, int out_size) {
    const float* in_feature = (const float*)d_in[0];   // [N, 256]
    const int*   edge_rows  = (const int*)d_in[1];     // [E]
    const int*   edge_cols  = (const int*)d_in[2];     // [E]
    const float* edge_vals  = (const float*)d_in[3];   // [E]
    const float* weight     = (const float*)d_in[4];   // [256, 128]
    const float* bias       = (const float*)d_in[5];   // [128]
    float*       out        = (float*)d_out;           // [N, 128]

    (void)in_sizes; (void)n_in; (void)out_size;

    // 1) support = X @ W
    gemm_kernel<<<(N_NODES + BM - 1) / BM, 256>>>(in_feature, weight);

    // 2) CSR build
    zero_counts_kernel<<<(N_NODES + 255) / 256, 256>>>();
    hist_kernel<<<(N_EDGES + 255) / 256, 256>>>(edge_rows);
    scan1_kernel<<<NSB, SCAN_B>>>();
    scan2_kernel<<<1, 32>>>();
    scan3_kernel<<<(N_NODES + 255) / 256, 256>>>();
    scatter_kernel<<<(N_EDGES + 255) / 256, 256>>>(edge_rows, edge_cols, edge_vals);

    // 3) out = A @ support + bias   (one warp per row)
    int warps_total = N_NODES;
    int blocks = (warps_total * 32 + 255) / 256;
    aggregate_kernel<<<blocks, 256>>>(bias, out);
}

// round 3
// speedup vs baseline: 1.4210x; 1.4210x over previous
#include <cuda_runtime.h>
#include <cuda_bf16.h>
#include <stdint.h>

#define N_NODES 100000
#define N_EDGES 1600000
#define D_IN    256
#define D_OUT   128
#define N_TILES ((N_NODES + 127) / 128)   // 782

// ---------------- device scratch (no allocations allowed) ----------------
__device__ float g_support[(size_t)N_NODES * D_OUT];   // X @ W   (51.2 MB)
__device__ int   g_counts[N_NODES];
__device__ int   g_rowptr[N_NODES + 1];
__device__ int   g_cursor[N_NODES];
__device__ int2  g_sorted_cv[N_EDGES];                 // (col, val-bits) sorted by row

// W split into bf16 hi/lo, K-major-pair padded layout: u32[n*132 + k/2]
#define WSTRIDE 132
__device__ uint32_t g_w_hi[128 * WSTRIDE];
__device__ uint32_t g_w_lo[128 * WSTRIDE];

#define SCAN_B 1024
#define NSB    ((N_NODES + SCAN_B - 1) / SCAN_B)       // 98
__device__ int   g_blocksums[NSB];

// ---------------- 0) W prep: split fp32 W -> bf16 hi/lo ------------------
__global__ void wprep_kernel(const float* __restrict__ W) {
    int idx = blockIdx.x * blockDim.x + threadIdx.x;   // 0..32767
    if (idx >= D_IN * D_OUT) return;
    int n = idx & 127;          // output col
    int k = idx >> 7;           // input dim (K)
    float w = W[(size_t)k * D_OUT + n];
    __nv_bfloat16 hb = __float2bfloat16(w);
    float hf = __bfloat162float(hb);
    __nv_bfloat16 lb = __float2bfloat16(w - hf);
    int u = n * WSTRIDE + (k >> 1);
    int h = k & 1;
    ((uint16_t*)&g_w_hi[u])[h] = *(uint16_t*)&hb;
    ((uint16_t*)&g_w_lo[u])[h] = *(uint16_t*)&lb;
}

// ---------------- 1) HMMA GEMM: support = X @ W --------------------------
// SMEM (u32 units):
//   w_hi  [128*132]                     (67584 B)
//   w_lo  [128*132]                     (67584 B)
//   a_buf [2 stages][2 terms][128*20]   (4 * 10240 B)
#define ASTRIDE 20
#define W_U32   (128 * WSTRIDE)
#define A_U32   (128 * ASTRIDE)
#define SM_TOTAL_B ((2 * W_U32 + 4 * A_U32) * 4)   // 176128 bytes

// pack two fp32 -> bf16x2 (f0 low half, f1 high half)
__device__ __forceinline__ uint32_t pack_bf(float f0, float f1) {
    uint32_t r;
    asm("cvt.rn.bf16x2.f32 %0, %1, %2;" : "=r"(r) : "f"(f1), "f"(f0));
    return r;
}

__device__ __forceinline__ void mma16816(float* d, const uint32_t* a, const uint32_t* b) {
    asm volatile(
        "mma.sync.aligned.m16n8k16.row.col.f32.bf16.bf16.f32 "
        "{%0,%1,%2,%3}, {%4,%5,%6,%7}, {%8,%9}, {%0,%1,%2,%3};"
        : "+f"(d[0]), "+f"(d[1]), "+f"(d[2]), "+f"(d[3])
        : "r"(a[0]), "r"(a[1]), "r"(a[2]), "r"(a[3]), "r"(b[0]), "r"(b[1]));
}

__global__ __launch_bounds__(256, 1)
void gemm_mma_kernel(const float* __restrict__ A) {
    extern __shared__ uint32_t smem[];
    uint32_t* w_hi  = smem;
    uint32_t* w_lo  = smem + W_U32;
    uint32_t* a_buf = smem + 2 * W_U32;   // [stage][term][A_U32]

    const int tid    = threadIdx.x;
    const int wid    = tid >> 5;
    const int lane   = tid & 31;
    const int warp_m = wid & 3;           // 4 row-bands of 32
    const int warp_n = wid >> 2;          // 2 col-bands of 64
    const int g      = lane >> 2;         // groupID
    const int c      = lane & 3;          // threadID_in_group

    // W hi/lo resident in SMEM (read once from gmem per CTA)
    for (int i = tid; i < W_U32; i += 256) { w_hi[i] = g_w_hi[i]; w_lo[i] = g_w_lo[i]; }
    __syncthreads();

    const int a_row  = tid >> 1;          // 0..127
    const int a_half = tid & 1;           // which 16-float half of the 32-k block

    for (int tile = blockIdx.x; tile < N_TILES; tile += gridDim.x) {
        const int m0 = tile * 128;

        float acc[2][8][4];
#pragma unroll
        for (int mt = 0; mt < 2; mt++)
#pragma unroll
            for (int nt = 0; nt < 8; nt++)
#pragma unroll
                for (int q = 0; q < 4; q++) acc[mt][nt][q] = 0.f;

        for (int kb = 0; kb < 8; kb++) {           // K blocks of 32
            const int stage = kb & 1;
            uint32_t* abh = a_buf + (stage * 2 + 0) * A_U32;
            uint32_t* abl = a_buf + (stage * 2 + 1) * A_U32;

            // ---- load + split A block [128 rows x 32 k] ----
            {
                const int gr = m0 + a_row;
                float4 v0, v1, v2, v3;
                if (gr < N_NODES) {
                    const float4* p = (const float4*)(A + (size_t)gr * D_IN + kb * 32 + a_half * 16);
                    v0 = p[0]; v1 = p[1]; v2 = p[2]; v3 = p[3];
                } else {
                    v0 = v1 = v2 = v3 = make_float4(0.f, 0.f, 0.f, 0.f);
                }
                float f[16] = {v0.x, v0.y, v0.z, v0.w, v1.x, v1.y, v1.z, v1.w,
                               v2.x, v2.y, v2.z, v2.w, v3.x, v3.y, v3.z, v3.w};
                uint32_t hi[8], lo[8];
#pragma unroll
                for (int q = 0; q < 8; q++) {
                    uint32_t hq = pack_bf(f[2 * q], f[2 * q + 1]);
                    float h0 = __uint_as_float(hq << 16);
                    float h1 = __uint_as_float(hq & 0xFFFF0000u);
                    hi[q] = hq;
                    lo[q] = pack_bf(f[2 * q] - h0, f[2 * q + 1] - h1);
                }
                uint32_t* dh = abh + a_row * ASTRIDE + a_half * 8;
                uint32_t* dl = abl + a_row * ASTRIDE + a_half * 8;
                *(uint4*)(dh + 0) = make_uint4(hi[0], hi[1], hi[2], hi[3]);
                *(uint4*)(dh + 4) = make_uint4(hi[4], hi[5], hi[6], hi[7]);
                *(uint4*)(dl + 0) = make_uint4(lo[0], lo[1], lo[2], lo[3]);
                *(uint4*)(dl + 4) = make_uint4(lo[4], lo[5], lo[6], lo[7]);
            }
            __syncthreads();

            // ---- compute: 2 k16 steps ----
#pragma unroll
            for (int kk = 0; kk < 2; kk++) {
                const int kpl = kk * 8 + c;                 // local kpair for A
                const int kpg = kb * 16 + kk * 8 + c;       // global kpair for W

                uint32_t ah[2][4], al[2][4];
#pragma unroll
                for (int mt = 0; mt < 2; mt++) {
                    const int r0 = (warp_m * 32 + mt * 16 + g) * ASTRIDE;
                    const int r1 = r0 + 8 * ASTRIDE;
                    ah[mt][0] = abh[r0 + kpl];     ah[mt][1] = abh[r1 + kpl];
                    ah[mt][2] = abh[r0 + kpl + 4]; ah[mt][3] = abh[r1 + kpl + 4];
                    al[mt][0] = abl[r0 + kpl];     al[mt][1] = abl[r1 + kpl];
                    al[mt][2] = abl[r0 + kpl + 4]; al[mt][3] = abl[r1 + kpl + 4];
                }
                uint32_t bh[8][2], bl[8][2];
#pragma unroll
                for (int nt = 0; nt < 8; nt++) {
                    const int n = warp_n * 64 + nt * 8 + g;
                    bh[nt][0] = w_hi[n * WSTRIDE + kpg];
                    bh[nt][1] = w_hi[n * WSTRIDE + kpg + 4];
                    bl[nt][0] = w_lo[n * WSTRIDE + kpg];
                    bl[nt][1] = w_lo[n * WSTRIDE + kpg + 4];
                }
#pragma unroll
                for (int mt = 0; mt < 2; mt++)
#pragma unroll
                    for (int nt = 0; nt < 8; nt++) {
                        mma16816(acc[mt][nt], ah[mt], bh[nt]);
                        mma16816(acc[mt][nt], al[mt], bh[nt]);
                        mma16816(acc[mt][nt], ah[mt], bl[nt]);
                    }
            }
        }

        // ---- epilogue ----
#pragma unroll
        for (int mt = 0; mt < 2; mt++) {
            const int r0 = m0 + warp_m * 32 + mt * 16 + g;
#pragma unroll
            for (int nt = 0; nt < 8; nt++) {
                const int col = warp_n * 64 + nt * 8 + 2 * c;
                if (r0 < N_NODES)
                    *(float2*)&g_support[(size_t)r0 * D_OUT + col] =
                        make_float2(acc[mt][nt][0], acc[mt][nt][1]);
                if (r0 + 8 < N_NODES)
                    *(float2*)&g_support[(size_t)(r0 + 8) * D_OUT + col] =
                        make_float2(acc[mt][nt][2], acc[mt][nt][3]);
            }
        }
        __syncthreads();   // protect A stages before next tile reuses them
    }
}

// ---------------- 2) CSR build: histogram -> scan -> scatter -------------
__global__ void zero_counts_kernel() {
    int i = blockIdx.x * blockDim.x + threadIdx.x;
    if (i < N_NODES) g_counts[i] = 0;
}

__global__ void hist_kernel(const int* __restrict__ rows) {
    int e = blockIdx.x * blockDim.x + threadIdx.x;
    if (e < N_EDGES) atomicAdd(&g_counts[rows[e]], 1);
}

__global__ __launch_bounds__(SCAN_B)
void scan1_kernel() {
    __shared__ int sh[SCAN_B];
    int i = blockIdx.x * SCAN_B + threadIdx.x;
    int v = (i < N_NODES) ? g_counts[i] : 0;
    sh[threadIdx.x] = v;
    __syncthreads();
#pragma unroll
    for (int off = 1; off < SCAN_B; off <<= 1) {
        int t = (threadIdx.x >= off) ? sh[threadIdx.x - off] : 0;
        __syncthreads();
        sh[threadIdx.x] += t;
        __syncthreads();
    }
    if (i < N_NODES) g_rowptr[i] = sh[threadIdx.x] - v;   // block-local exclusive
    if (threadIdx.x == SCAN_B - 1) g_blocksums[blockIdx.x] = sh[SCAN_B - 1];
}

__global__ __launch_bounds__(128)
void scan2_kernel() {    // parallel exclusive scan of the 98 block sums
    __shared__ int sh[128];
    int t = threadIdx.x;
    int v = (t < NSB) ? g_blocksums[t] : 0;
    sh[t] = v;
    __syncthreads();
#pragma unroll
    for (int off = 1; off < 128; off <<= 1) {
        int x = (t >= off) ? sh[t - off] : 0;
        __syncthreads();
        sh[t] += x;
        __syncthreads();
    }
    if (t < NSB) g_blocksums[t] = sh[t] - v;
}

__global__ void scan3_kernel() {
    int i = blockIdx.x * blockDim.x + threadIdx.x;
    if (i < N_NODES) {
        int v = g_rowptr[i] + g_blocksums[i / SCAN_B];
        g_rowptr[i] = v;
        g_cursor[i] = v;
    }
    if (i == 0) g_rowptr[N_NODES] = N_EDGES;
}

__global__ void scatter_kernel(const int* __restrict__ rows,
                               const int* __restrict__ cols,
                               const float* __restrict__ vals) {
    int e = blockIdx.x * blockDim.x + threadIdx.x;
    if (e >= N_EDGES) return;
    int r = rows[e];
    int p = atomicAdd(&g_cursor[r], 1);
    g_sorted_cv[p] = make_int2(cols[e], __float_as_int(vals[e]));
}

// ---------------- 3) Aggregate: one warp per row, no atomics -------------
__global__ __launch_bounds__(256)
void aggregate_kernel(const float* __restrict__ bias, float* __restrict__ out) {
    int w    = (blockIdx.x * blockDim.x + threadIdx.x) >> 5;   // row id
    int lane = threadIdx.x & 31;
    if (w >= N_NODES) return;

    int s = g_rowptr[w];
    int e = g_rowptr[w + 1];

    float4 acc = make_float4(0.f, 0.f, 0.f, 0.f);
    int j = s;
    // unroll-by-4 for gather MLP
    for (; j + 3 < e; j += 4) {
        int2 cv0 = g_sorted_cv[j];
        int2 cv1 = g_sorted_cv[j + 1];
        int2 cv2 = g_sorted_cv[j + 2];
        int2 cv3 = g_sorted_cv[j + 3];
        float4 s0 = *(const float4*)&g_support[(size_t)cv0.x * D_OUT + lane * 4];
        float4 s1 = *(const float4*)&g_support[(size_t)cv1.x * D_OUT + lane * 4];
        float4 s2 = *(const float4*)&g_support[(size_t)cv2.x * D_OUT + lane * 4];
        float4 s3 = *(const float4*)&g_support[(size_t)cv3.x * D_OUT + lane * 4];
        float v0 = __int_as_float(cv0.y), v1 = __int_as_float(cv1.y);
        float v2 = __int_as_float(cv2.y), v3 = __int_as_float(cv3.y);
        acc.x += v0 * s0.x; acc.y += v0 * s0.y; acc.z += v0 * s0.z; acc.w += v0 * s0.w;
        acc.x += v1 * s1.x; acc.y += v1 * s1.y; acc.z += v1 * s1.z; acc.w += v1 * s1.w;
        acc.x += v2 * s2.x; acc.y += v2 * s2.y; acc.z += v2 * s2.z; acc.w += v2 * s2.w;
        acc.x += v3 * s3.x; acc.y += v3 * s3.y; acc.z += v3 * s3.z; acc.w += v3 * s3.w;
    }
    for (; j < e; j++) {
        int2 cv = g_sorted_cv[j];
        float v = __int_as_float(cv.y);
        float4 s0 = *(const float4*)&g_support[(size_t)cv.x * D_OUT + lane * 4];
        acc.x += v * s0.x; acc.y += v * s0.y; acc.z += v * s0.z; acc.w += v * s0.w;
    }

    float4 b = ((const float4*)bias)[lane];
    acc.x += b.x; acc.y += b.y; acc.z += b.z; acc.w += b.w;
    *(float4*)&out[(size_t)w * D_OUT + lane * 4] = acc;
}

// ---------------- launch ------------------------------------------------
extern "C" void kernel_launch(void* const* d_in, const int* in_sizes, int n_in,
                              void* d_out, int out_size) {
    const float* in_feature = (const float*)d_in[0];   // [N, 256]
    const int*   edge_rows  = (const int*)d_in[1];     // [E]
    const int*   edge_cols  = (const int*)d_in[2];     // [E]
    const float* edge_vals  = (const float*)d_in[3];   // [E]
    const float* weight     = (const float*)d_in[4];   // [256, 128]
    const float* bias       = (const float*)d_in[5];   // [128]
    float*       out        = (float*)d_out;           // [N, 128]

    (void)in_sizes; (void)n_in; (void)out_size;

    static int smem_cfg_done = 0;
    if (!smem_cfg_done) {
        cudaFuncSetAttribute(gemm_mma_kernel, cudaFuncAttributeMaxDynamicSharedMemorySize, SM_TOTAL_B);
        smem_cfg_done = 1;
    }

    // 0) W split, 1) support = X @ W  (HMMA tensor pipe)
    wprep_kernel<<<(D_IN * D_OUT + 255) / 256, 256>>>(weight);
    gemm_mma_kernel<<<148, 256, SM_TOTAL_B>>>(in_feature);

    // 2) CSR build
    zero_counts_kernel<<<(N_NODES + 255) / 256, 256>>>();
    hist_kernel<<<(N_EDGES + 255) / 256, 256>>>(edge_rows);
    scan1_kernel<<<NSB, SCAN_B>>>();
    scan2_kernel<<<1, 128>>>();
    scan3_kernel<<<(N_NODES + 255) / 256, 256>>>();
    scatter_kernel<<<(N_EDGES + 255) / 256, 256>>>(edge_rows, edge_cols, edge_vals);

    // 3) out = A @ support + bias   (one warp per row)
    int blocks = (N_NODES * 32 + 255) / 256;
    aggregate_kernel<<<blocks, 256>>>(bias, out);
}

// round 4
// speedup vs baseline: 1.5490x; 1.0901x over previous
#include <cuda_runtime.h>
#include <cuda_bf16.h>
#include <stdint.h>

#define N_NODES 100000
#define N_EDGES 1600000
#define D_IN    256
#define D_OUT   128
#define N_TILES ((N_NODES + 127) / 128)   // 782

// ---------------- device scratch (no allocations allowed) ----------------
__device__ float g_support[(size_t)N_NODES * D_OUT];   // X @ W   (51.2 MB)
__device__ int   g_counts[N_NODES];
__device__ int   g_rowptr[N_NODES + 1];
__device__ int   g_cursor[N_NODES];
__device__ int2  g_sorted_cv[N_EDGES];                 // (col, val-bits) sorted by row

// W split into bf16 hi/lo, K-major-pair padded layout: u32[n*132 + k/2]
#define WSTRIDE 132
__device__ uint32_t g_w_hi[128 * WSTRIDE];
__device__ uint32_t g_w_lo[128 * WSTRIDE];

#define SCAN_B 1024
#define NSB    ((N_NODES + SCAN_B - 1) / SCAN_B)       // 98
__device__ int   g_blocksums[NSB];

// ---------------- 0) W prep: split fp32 W -> bf16 hi/lo ------------------
__global__ void wprep_kernel(const float* __restrict__ W) {
    int idx = blockIdx.x * blockDim.x + threadIdx.x;   // 0..32767
    if (idx >= D_IN * D_OUT) return;
    int n = idx & 127;          // output col
    int k = idx >> 7;           // input dim (K)
    float w = W[(size_t)k * D_OUT + n];
    __nv_bfloat16 hb = __float2bfloat16(w);
    float hf = __bfloat162float(hb);
    __nv_bfloat16 lb = __float2bfloat16(w - hf);
    int u = n * WSTRIDE + (k >> 1);
    int h = k & 1;
    ((uint16_t*)&g_w_hi[u])[h] = *(uint16_t*)&hb;
    ((uint16_t*)&g_w_lo[u])[h] = *(uint16_t*)&lb;
}

// ---------------- 1) HMMA GEMM: support = X @ W --------------------------
#define ASTRIDE 20
#define W_U32   (128 * WSTRIDE)
#define A_U32   (128 * ASTRIDE)
#define SM_TOTAL_B ((2 * W_U32 + 4 * A_U32) * 4)   // 176128 bytes

// pack two fp32 -> bf16x2 (f0 low half, f1 high half)
__device__ __forceinline__ uint32_t pack_bf(float f0, float f1) {
    uint32_t r;
    asm("cvt.rn.bf16x2.f32 %0, %1, %2;" : "=r"(r) : "f"(f1), "f"(f0));
    return r;
}

__device__ __forceinline__ void mma16816(float* d, const uint32_t* a, const uint32_t* b) {
    asm volatile(
        "mma.sync.aligned.m16n8k16.row.col.f32.bf16.bf16.f32 "
        "{%0,%1,%2,%3}, {%4,%5,%6,%7}, {%8,%9}, {%0,%1,%2,%3};"
        : "+f"(d[0]), "+f"(d[1]), "+f"(d[2]), "+f"(d[3])
        : "r"(a[0]), "r"(a[1]), "r"(a[2]), "r"(a[3]), "r"(b[0]), "r"(b[1]));
}

__global__ __launch_bounds__(256, 1)
void gemm_mma_kernel(const float* __restrict__ A) {
    extern __shared__ uint32_t smem[];
    uint32_t* w_hi  = smem;
    uint32_t* w_lo  = smem + W_U32;
    uint32_t* a_buf = smem + 2 * W_U32;   // [stage][term][A_U32]

    const int tid    = threadIdx.x;
    const int wid    = tid >> 5;
    const int lane   = tid & 31;
    const int warp_m = wid & 3;           // 4 row-bands of 32
    const int warp_n = wid >> 2;          // 2 col-bands of 64
    const int g      = lane >> 2;         // groupID
    const int c      = lane & 3;          // threadID_in_group

    // W hi/lo resident in SMEM (read once from gmem per CTA)
    for (int i = tid; i < W_U32; i += 256) { w_hi[i] = g_w_hi[i]; w_lo[i] = g_w_lo[i]; }
    __syncthreads();

    const int a_row  = tid >> 1;          // 0..127
    const int a_half = tid & 1;           // which 16-float half of the 32-k block

    for (int tile = blockIdx.x; tile < N_TILES; tile += gridDim.x) {
        const int m0 = tile * 128;

        float acc[2][8][4];
#pragma unroll
        for (int mt = 0; mt < 2; mt++)
#pragma unroll
            for (int nt = 0; nt < 8; nt++)
#pragma unroll
                for (int q = 0; q < 4; q++) acc[mt][nt][q] = 0.f;

        for (int kb = 0; kb < 8; kb++) {           // K blocks of 32
            const int stage = kb & 1;
            uint32_t* abh = a_buf + (stage * 2 + 0) * A_U32;
            uint32_t* abl = a_buf + (stage * 2 + 1) * A_U32;

            // ---- load + split A block [128 rows x 32 k] ----
            {
                const int gr = m0 + a_row;
                float4 v0, v1, v2, v3;
                if (gr < N_NODES) {
                    const float4* p = (const float4*)(A + (size_t)gr * D_IN + kb * 32 + a_half * 16);
                    v0 = p[0]; v1 = p[1]; v2 = p[2]; v3 = p[3];
                } else {
                    v0 = v1 = v2 = v3 = make_float4(0.f, 0.f, 0.f, 0.f);
                }
                float f[16] = {v0.x, v0.y, v0.z, v0.w, v1.x, v1.y, v1.z, v1.w,
                               v2.x, v2.y, v2.z, v2.w, v3.x, v3.y, v3.z, v3.w};
                uint32_t hi[8], lo[8];
#pragma unroll
                for (int q = 0; q < 8; q++) {
                    uint32_t hq = pack_bf(f[2 * q], f[2 * q + 1]);
                    float h0 = __uint_as_float(hq << 16);
                    float h1 = __uint_as_float(hq & 0xFFFF0000u);
                    hi[q] = hq;
                    lo[q] = pack_bf(f[2 * q] - h0, f[2 * q + 1] - h1);
                }
                uint32_t* dh = abh + a_row * ASTRIDE + a_half * 8;
                uint32_t* dl = abl + a_row * ASTRIDE + a_half * 8;
                *(uint4*)(dh + 0) = make_uint4(hi[0], hi[1], hi[2], hi[3]);
                *(uint4*)(dh + 4) = make_uint4(hi[4], hi[5], hi[6], hi[7]);
                *(uint4*)(dl + 0) = make_uint4(lo[0], lo[1], lo[2], lo[3]);
                *(uint4*)(dl + 4) = make_uint4(lo[4], lo[5], lo[6], lo[7]);
            }
            __syncthreads();

            // ---- compute: 2 k16 steps ----
#pragma unroll
            for (int kk = 0; kk < 2; kk++) {
                const int kpl = kk * 8 + c;                 // local kpair for A
                const int kpg = kb * 16 + kk * 8 + c;       // global kpair for W

                uint32_t ah[2][4], al[2][4];
#pragma unroll
                for (int mt = 0; mt < 2; mt++) {
                    const int r0 = (warp_m * 32 + mt * 16 + g) * ASTRIDE;
                    const int r1 = r0 + 8 * ASTRIDE;
                    ah[mt][0] = abh[r0 + kpl];     ah[mt][1] = abh[r1 + kpl];
                    ah[mt][2] = abh[r0 + kpl + 4]; ah[mt][3] = abh[r1 + kpl + 4];
                    al[mt][0] = abl[r0 + kpl];     al[mt][1] = abl[r1 + kpl];
                    al[mt][2] = abl[r0 + kpl + 4]; al[mt][3] = abl[r1 + kpl + 4];
                }
                uint32_t bh[8][2], bl[8][2];
#pragma unroll
                for (int nt = 0; nt < 8; nt++) {
                    const int n = warp_n * 64 + nt * 8 + g;
                    bh[nt][0] = w_hi[n * WSTRIDE + kpg];
                    bh[nt][1] = w_hi[n * WSTRIDE + kpg + 4];
                    bl[nt][0] = w_lo[n * WSTRIDE + kpg];
                    bl[nt][1] = w_lo[n * WSTRIDE + kpg + 4];
                }
#pragma unroll
                for (int mt = 0; mt < 2; mt++)
#pragma unroll
                    for (int nt = 0; nt < 8; nt++) {
                        mma16816(acc[mt][nt], ah[mt], bh[nt]);
                        mma16816(acc[mt][nt], al[mt], bh[nt]);
                        mma16816(acc[mt][nt], ah[mt], bl[nt]);
                    }
            }
        }

        // ---- epilogue ----
#pragma unroll
        for (int mt = 0; mt < 2; mt++) {
            const int r0 = m0 + warp_m * 32 + mt * 16 + g;
#pragma unroll
            for (int nt = 0; nt < 8; nt++) {
                const int col = warp_n * 64 + nt * 8 + 2 * c;
                if (r0 < N_NODES)
                    *(float2*)&g_support[(size_t)r0 * D_OUT + col] =
                        make_float2(acc[mt][nt][0], acc[mt][nt][1]);
                if (r0 + 8 < N_NODES)
                    *(float2*)&g_support[(size_t)(r0 + 8) * D_OUT + col] =
                        make_float2(acc[mt][nt][2], acc[mt][nt][3]);
            }
        }
        __syncthreads();   // protect A stages before next tile reuses them
    }
}

// ---------------- 2) CSR build: histogram -> scan -> scatter -------------
// hist: 4 edges per thread, vectorized
__global__ void hist4_kernel(const int* __restrict__ rows) {
    int t = blockIdx.x * blockDim.x + threadIdx.x;
    if (t * 4 >= N_EDGES) return;
    int4 r = ((const int4*)rows)[t];
    atomicAdd(&g_counts[r.x], 1);
    atomicAdd(&g_counts[r.y], 1);
    atomicAdd(&g_counts[r.z], 1);
    atomicAdd(&g_counts[r.w], 1);
}

__global__ __launch_bounds__(SCAN_B)
void scan1_kernel() {
    __shared__ int sh[SCAN_B];
    int i = blockIdx.x * SCAN_B + threadIdx.x;
    int v = (i < N_NODES) ? g_counts[i] : 0;
    sh[threadIdx.x] = v;
    __syncthreads();
#pragma unroll
    for (int off = 1; off < SCAN_B; off <<= 1) {
        int t = (threadIdx.x >= off) ? sh[threadIdx.x - off] : 0;
        __syncthreads();
        sh[threadIdx.x] += t;
        __syncthreads();
    }
    if (i < N_NODES) g_rowptr[i] = sh[threadIdx.x] - v;   // block-local exclusive
    if (threadIdx.x == SCAN_B - 1) g_blocksums[blockIdx.x] = sh[SCAN_B - 1];
}

__global__ __launch_bounds__(128)
void scan2_kernel() {    // parallel exclusive scan of the 98 block sums
    __shared__ int sh[128];
    int t = threadIdx.x;
    int v = (t < NSB) ? g_blocksums[t] : 0;
    sh[t] = v;
    __syncthreads();
#pragma unroll
    for (int off = 1; off < 128; off <<= 1) {
        int x = (t >= off) ? sh[t - off] : 0;
        __syncthreads();
        sh[t] += x;
        __syncthreads();
    }
    if (t < NSB) g_blocksums[t] = sh[t] - v;
}

__global__ void scan3_kernel() {
    int i = blockIdx.x * blockDim.x + threadIdx.x;
    if (i < N_NODES) {
        int v = g_rowptr[i] + g_blocksums[i / SCAN_B];
        g_rowptr[i] = v;
        g_cursor[i] = v;
    }
    if (i == 0) g_rowptr[N_NODES] = N_EDGES;
}

// scatter: 4 edges per thread, vectorized loads
__global__ void scatter4_kernel(const int* __restrict__ rows,
                                const int* __restrict__ cols,
                                const float* __restrict__ vals) {
    int t = blockIdx.x * blockDim.x + threadIdx.x;
    if (t * 4 >= N_EDGES) return;
    int4   r = ((const int4*)rows)[t];
    int4   c = ((const int4*)cols)[t];
    float4 v = ((const float4*)vals)[t];
    int p0 = atomicAdd(&g_cursor[r.x], 1);
    int p1 = atomicAdd(&g_cursor[r.y], 1);
    int p2 = atomicAdd(&g_cursor[r.z], 1);
    int p3 = atomicAdd(&g_cursor[r.w], 1);
    g_sorted_cv[p0] = make_int2(c.x, __float_as_int(v.x));
    g_sorted_cv[p1] = make_int2(c.y, __float_as_int(v.y));
    g_sorted_cv[p2] = make_int2(c.z, __float_as_int(v.z));
    g_sorted_cv[p3] = make_int2(c.w, __float_as_int(v.w));
}

// ---------------- 3) Aggregate: one warp per row, no atomics -------------
__global__ __launch_bounds__(256)
void aggregate_kernel(const float* __restrict__ bias, float* __restrict__ out) {
    int w    = (blockIdx.x * blockDim.x + threadIdx.x) >> 5;   // row id
    int lane = threadIdx.x & 31;
    if (w >= N_NODES) return;

    int s = g_rowptr[w];
    int e = g_rowptr[w + 1];

    float4 acc = make_float4(0.f, 0.f, 0.f, 0.f);
    int j = s;
    // unroll-by-4 for gather MLP
    for (; j + 3 < e; j += 4) {
        int2 cv0 = g_sorted_cv[j];
        int2 cv1 = g_sorted_cv[j + 1];
        int2 cv2 = g_sorted_cv[j + 2];
        int2 cv3 = g_sorted_cv[j + 3];
        float4 s0 = *(const float4*)&g_support[(size_t)cv0.x * D_OUT + lane * 4];
        float4 s1 = *(const float4*)&g_support[(size_t)cv1.x * D_OUT + lane * 4];
        float4 s2 = *(const float4*)&g_support[(size_t)cv2.x * D_OUT + lane * 4];
        float4 s3 = *(const float4*)&g_support[(size_t)cv3.x * D_OUT + lane * 4];
        float v0 = __int_as_float(cv0.y), v1 = __int_as_float(cv1.y);
        float v2 = __int_as_float(cv2.y), v3 = __int_as_float(cv3.y);
        acc.x += v0 * s0.x; acc.y += v0 * s0.y; acc.z += v0 * s0.z; acc.w += v0 * s0.w;
        acc.x += v1 * s1.x; acc.y += v1 * s1.y; acc.z += v1 * s1.z; acc.w += v1 * s1.w;
        acc.x += v2 * s2.x; acc.y += v2 * s2.y; acc.z += v2 * s2.z; acc.w += v2 * s2.w;
        acc.x += v3 * s3.x; acc.y += v3 * s3.y; acc.z += v3 * s3.z; acc.w += v3 * s3.w;
    }
    for (; j < e; j++) {
        int2 cv = g_sorted_cv[j];
        float v = __int_as_float(cv.y);
        float4 s0 = *(const float4*)&g_support[(size_t)cv.x * D_OUT + lane * 4];
        acc.x += v * s0.x; acc.y += v * s0.y; acc.z += v * s0.z; acc.w += v * s0.w;
    }

    float4 b = ((const float4*)bias)[lane];
    acc.x += b.x; acc.y += b.y; acc.z += b.z; acc.w += b.w;
    *(float4*)&out[(size_t)w * D_OUT + lane * 4] = acc;
}

// ---------------- launch ------------------------------------------------
extern "C" void kernel_launch(void* const* d_in, const int* in_sizes, int n_in,
                              void* d_out, int out_size) {
    const float* in_feature = (const float*)d_in[0];   // [N, 256]
    const int*   edge_rows  = (const int*)d_in[1];     // [E]
    const int*   edge_cols  = (const int*)d_in[2];     // [E]
    const float* edge_vals  = (const float*)d_in[3];   // [E]
    const float* weight     = (const float*)d_in[4];   // [256, 128]
    const float* bias       = (const float*)d_in[5];   // [128]
    float*       out        = (float*)d_out;           // [N, 128]

    (void)in_sizes; (void)n_in; (void)out_size;

    static cudaStream_t s2 = 0;
    static cudaEvent_t ev_fork = 0, ev_join = 0;
    static void* counts_ptr = 0;
    static int init_done = 0;
    if (!init_done) {
        cudaFuncSetAttribute(gemm_mma_kernel, cudaFuncAttributeMaxDynamicSharedMemorySize, SM_TOTAL_B);
        cudaStreamCreateWithFlags(&s2, cudaStreamNonBlocking);
        cudaEventCreateWithFlags(&ev_fork, cudaEventDisableTiming);
        cudaEventCreateWithFlags(&ev_join, cudaEventDisableTiming);
        cudaGetSymbolAddress(&counts_ptr, g_counts);
        init_done = 1;
    }

    // fork: CSR build runs concurrently with the GEMM path
    cudaEventRecord(ev_fork, 0);
    cudaStreamWaitEvent(s2, ev_fork, 0);

    // --- main stream: W split + GEMM (tensor pipe / DRAM-bound) ---
    wprep_kernel<<<(D_IN * D_OUT + 255) / 256, 256>>>(weight);
    gemm_mma_kernel<<<148, 256, SM_TOTAL_B>>>(in_feature);

    // --- s2: CSR build (L2-atomic-bound) ---
    cudaMemsetAsync(counts_ptr, 0, N_NODES * sizeof(int), s2);
    hist4_kernel<<<(N_EDGES / 4 + 255) / 256, 256, 0, s2>>>(edge_rows);
    scan1_kernel<<<NSB, SCAN_B, 0, s2>>>();
    scan2_kernel<<<1, 128, 0, s2>>>();
    scan3_kernel<<<(N_NODES + 255) / 256, 256, 0, s2>>>();
    scatter4_kernel<<<(N_EDGES / 4 + 255) / 256, 256, 0, s2>>>(edge_rows, edge_cols, edge_vals);

    // join
    cudaEventRecord(ev_join, s2);
    cudaStreamWaitEvent(0, ev_join, 0);

    // 3) out = A @ support + bias   (one warp per row)
    int blocks = (N_NODES * 32 + 255) / 256;
    aggregate_kernel<<<blocks, 256>>>(bias, out);
}

// round 5
// speedup vs baseline: 1.6690x; 1.0775x over previous
#include <cuda_runtime.h>
#include <cuda_bf16.h>
#include <cuda_fp16.h>
#include <stdint.h>

#define N_NODES 100000
#define N_EDGES 1600000
#define D_IN    256
#define D_OUT   128
#define N_TILES ((N_NODES + 127) / 128)   // 782

// ---------------- device scratch (no allocations allowed) ----------------
// support stored as fp16, packed half2 in u32: [N_NODES][64] u32
__device__ uint32_t g_support_h[(size_t)N_NODES * (D_OUT / 2)];   // 25.6 MB
__device__ int   g_counts[N_NODES];
__device__ int   g_rowptr[N_NODES + 1];
__device__ int   g_cursor[N_NODES];
__device__ int2  g_sorted_cv[N_EDGES];                 // (col, val-bits) sorted by row

// W split into bf16 hi/lo, K-major-pair padded layout: u32[n*132 + k/2]
#define WSTRIDE 132
__device__ uint32_t g_w_hi[128 * WSTRIDE];
__device__ uint32_t g_w_lo[128 * WSTRIDE];

#define SCAN_B 1024
#define NSB    ((N_NODES + SCAN_B - 1) / SCAN_B)       // 98
__device__ int   g_blocksums[NSB];

// ---------------- 0) W prep: split fp32 W -> bf16 hi/lo ------------------
__global__ void wprep_kernel(const float* __restrict__ W) {
    int idx = blockIdx.x * blockDim.x + threadIdx.x;   // 0..32767
    if (idx >= D_IN * D_OUT) return;
    int n = idx & 127;          // output col
    int k = idx >> 7;           // input dim (K)
    float w = W[(size_t)k * D_OUT + n];
    __nv_bfloat16 hb = __float2bfloat16(w);
    float hf = __bfloat162float(hb);
    __nv_bfloat16 lb = __float2bfloat16(w - hf);
    int u = n * WSTRIDE + (k >> 1);
    int h = k & 1;
    ((uint16_t*)&g_w_hi[u])[h] = *(uint16_t*)&hb;
    ((uint16_t*)&g_w_lo[u])[h] = *(uint16_t*)&lb;
}

// ---------------- 1) HMMA GEMM: support = X @ W (fp16 output) ------------
#define ASTRIDE 20
#define W_U32   (128 * WSTRIDE)
#define A_U32   (128 * ASTRIDE)
#define SM_TOTAL_B ((2 * W_U32 + 4 * A_U32) * 4)   // 176128 bytes

// pack two fp32 -> bf16x2 (f0 low half, f1 high half)
__device__ __forceinline__ uint32_t pack_bf(float f0, float f1) {
    uint32_t r;
    asm("cvt.rn.bf16x2.f32 %0, %1, %2;" : "=r"(r) : "f"(f1), "f"(f0));
    return r;
}

__device__ __forceinline__ void mma16816(float* d, const uint32_t* a, const uint32_t* b) {
    asm volatile(
        "mma.sync.aligned.m16n8k16.row.col.f32.bf16.bf16.f32 "
        "{%0,%1,%2,%3}, {%4,%5,%6,%7}, {%8,%9}, {%0,%1,%2,%3};"
        : "+f"(d[0]), "+f"(d[1]), "+f"(d[2]), "+f"(d[3])
        : "r"(a[0]), "r"(a[1]), "r"(a[2]), "r"(a[3]), "r"(b[0]), "r"(b[1]));
}

__global__ __launch_bounds__(256, 1)
void gemm_mma_kernel(const float* __restrict__ A) {
    extern __shared__ uint32_t smem[];
    uint32_t* w_hi  = smem;
    uint32_t* w_lo  = smem + W_U32;
    uint32_t* a_buf = smem + 2 * W_U32;   // [stage][term][A_U32]

    const int tid    = threadIdx.x;
    const int wid    = tid >> 5;
    const int lane   = tid & 31;
    const int warp_m = wid & 3;           // 4 row-bands of 32
    const int warp_n = wid >> 2;          // 2 col-bands of 64
    const int g      = lane >> 2;         // groupID
    const int c      = lane & 3;          // threadID_in_group

    // W hi/lo resident in SMEM (read once from gmem per CTA)
    for (int i = tid; i < W_U32; i += 256) { w_hi[i] = g_w_hi[i]; w_lo[i] = g_w_lo[i]; }
    __syncthreads();

    const int a_row  = tid >> 1;          // 0..127
    const int a_half = tid & 1;           // which 16-float half of the 32-k block

    for (int tile = blockIdx.x; tile < N_TILES; tile += gridDim.x) {
        const int m0 = tile * 128;

        float acc[2][8][4];
#pragma unroll
        for (int mt = 0; mt < 2; mt++)
#pragma unroll
            for (int nt = 0; nt < 8; nt++)
#pragma unroll
                for (int q = 0; q < 4; q++) acc[mt][nt][q] = 0.f;

        for (int kb = 0; kb < 8; kb++) {           // K blocks of 32
            const int stage = kb & 1;
            uint32_t* abh = a_buf + (stage * 2 + 0) * A_U32;
            uint32_t* abl = a_buf + (stage * 2 + 1) * A_U32;

            // ---- load + split A block [128 rows x 32 k] ----
            {
                const int gr = m0 + a_row;
                float4 v0, v1, v2, v3;
                if (gr < N_NODES) {
                    const float4* p = (const float4*)(A + (size_t)gr * D_IN + kb * 32 + a_half * 16);
                    v0 = p[0]; v1 = p[1]; v2 = p[2]; v3 = p[3];
                } else {
                    v0 = v1 = v2 = v3 = make_float4(0.f, 0.f, 0.f, 0.f);
                }
                float f[16] = {v0.x, v0.y, v0.z, v0.w, v1.x, v1.y, v1.z, v1.w,
                               v2.x, v2.y, v2.z, v2.w, v3.x, v3.y, v3.z, v3.w};
                uint32_t hi[8], lo[8];
#pragma unroll
                for (int q = 0; q < 8; q++) {
                    uint32_t hq = pack_bf(f[2 * q], f[2 * q + 1]);
                    float h0 = __uint_as_float(hq << 16);
                    float h1 = __uint_as_float(hq & 0xFFFF0000u);
                    hi[q] = hq;
                    lo[q] = pack_bf(f[2 * q] - h0, f[2 * q + 1] - h1);
                }
                uint32_t* dh = abh + a_row * ASTRIDE + a_half * 8;
                uint32_t* dl = abl + a_row * ASTRIDE + a_half * 8;
                *(uint4*)(dh + 0) = make_uint4(hi[0], hi[1], hi[2], hi[3]);
                *(uint4*)(dh + 4) = make_uint4(hi[4], hi[5], hi[6], hi[7]);
                *(uint4*)(dl + 0) = make_uint4(lo[0], lo[1], lo[2], lo[3]);
                *(uint4*)(dl + 4) = make_uint4(lo[4], lo[5], lo[6], lo[7]);
            }
            __syncthreads();

            // ---- compute: 2 k16 steps ----
#pragma unroll
            for (int kk = 0; kk < 2; kk++) {
                const int kpl = kk * 8 + c;                 // local kpair for A
                const int kpg = kb * 16 + kk * 8 + c;       // global kpair for W

                uint32_t ah[2][4], al[2][4];
#pragma unroll
                for (int mt = 0; mt < 2; mt++) {
                    const int r0 = (warp_m * 32 + mt * 16 + g) * ASTRIDE;
                    const int r1 = r0 + 8 * ASTRIDE;
                    ah[mt][0] = abh[r0 + kpl];     ah[mt][1] = abh[r1 + kpl];
                    ah[mt][2] = abh[r0 + kpl + 4]; ah[mt][3] = abh[r1 + kpl + 4];
                    al[mt][0] = abl[r0 + kpl];     al[mt][1] = abl[r1 + kpl];
                    al[mt][2] = abl[r0 + kpl + 4]; al[mt][3] = abl[r1 + kpl + 4];
                }
                uint32_t bh[8][2], bl[8][2];
#pragma unroll
                for (int nt = 0; nt < 8; nt++) {
                    const int n = warp_n * 64 + nt * 8 + g;
                    bh[nt][0] = w_hi[n * WSTRIDE + kpg];
                    bh[nt][1] = w_hi[n * WSTRIDE + kpg + 4];
                    bl[nt][0] = w_lo[n * WSTRIDE + kpg];
                    bl[nt][1] = w_lo[n * WSTRIDE + kpg + 4];
                }
#pragma unroll
                for (int mt = 0; mt < 2; mt++)
#pragma unroll
                    for (int nt = 0; nt < 8; nt++) {
                        mma16816(acc[mt][nt], ah[mt], bh[nt]);
                        mma16816(acc[mt][nt], al[mt], bh[nt]);
                        mma16816(acc[mt][nt], ah[mt], bl[nt]);
                    }
            }
        }

        // ---- epilogue: convert to fp16 (half2 per u32) ----
#pragma unroll
        for (int mt = 0; mt < 2; mt++) {
            const int r0 = m0 + warp_m * 32 + mt * 16 + g;
#pragma unroll
            for (int nt = 0; nt < 8; nt++) {
                // acc[..][0..1] = cols (2c, 2c+1) of row r0; [2..3] = row r0+8
                const int u = warp_n * 32 + nt * 4 + c;     // u32 col index
                if (r0 < N_NODES) {
                    __half2 h = __floats2half2_rn(acc[mt][nt][0], acc[mt][nt][1]);
                    g_support_h[(size_t)r0 * (D_OUT / 2) + u] = *(uint32_t*)&h;
                }
                if (r0 + 8 < N_NODES) {
                    __half2 h = __floats2half2_rn(acc[mt][nt][2], acc[mt][nt][3]);
                    g_support_h[(size_t)(r0 + 8) * (D_OUT / 2) + u] = *(uint32_t*)&h;
                }
            }
        }
        __syncthreads();   // protect A stages before next tile reuses them
    }
}

// ---------------- 2) CSR build: histogram -> scan -> scatter -------------
__global__ void hist4_kernel(const int* __restrict__ rows) {
    int t = blockIdx.x * blockDim.x + threadIdx.x;
    if (t * 4 >= N_EDGES) return;
    int4 r = ((const int4*)rows)[t];
    atomicAdd(&g_counts[r.x], 1);
    atomicAdd(&g_counts[r.y], 1);
    atomicAdd(&g_counts[r.z], 1);
    atomicAdd(&g_counts[r.w], 1);
}

__global__ __launch_bounds__(SCAN_B)
void scan1_kernel() {
    __shared__ int sh[SCAN_B];
    int i = blockIdx.x * SCAN_B + threadIdx.x;
    int v = (i < N_NODES) ? g_counts[i] : 0;
    sh[threadIdx.x] = v;
    __syncthreads();
#pragma unroll
    for (int off = 1; off < SCAN_B; off <<= 1) {
        int t = (threadIdx.x >= off) ? sh[threadIdx.x - off] : 0;
        __syncthreads();
        sh[threadIdx.x] += t;
        __syncthreads();
    }
    if (i < N_NODES) g_rowptr[i] = sh[threadIdx.x] - v;   // block-local exclusive
    if (threadIdx.x == SCAN_B - 1) g_blocksums[blockIdx.x] = sh[SCAN_B - 1];
}

__global__ __launch_bounds__(128)
void scan2_kernel() {    // parallel exclusive scan of the 98 block sums
    __shared__ int sh[128];
    int t = threadIdx.x;
    int v = (t < NSB) ? g_blocksums[t] : 0;
    sh[t] = v;
    __syncthreads();
#pragma unroll
    for (int off = 1; off < 128; off <<= 1) {
        int x = (t >= off) ? sh[t - off] : 0;
        __syncthreads();
        sh[t] += x;
        __syncthreads();
    }
    if (t < NSB) g_blocksums[t] = sh[t] - v;
}

__global__ void scan3_kernel() {
    int i = blockIdx.x * blockDim.x + threadIdx.x;
    if (i < N_NODES) {
        int v = g_rowptr[i] + g_blocksums[i / SCAN_B];
        g_rowptr[i] = v;
        g_cursor[i] = v;
    }
    if (i == 0) g_rowptr[N_NODES] = N_EDGES;
}

__global__ void scatter4_kernel(const int* __restrict__ rows,
                                const int* __restrict__ cols,
                                const float* __restrict__ vals) {
    int t = blockIdx.x * blockDim.x + threadIdx.x;
    if (t * 4 >= N_EDGES) return;
    int4   r = ((const int4*)rows)[t];
    int4   c = ((const int4*)cols)[t];
    float4 v = ((const float4*)vals)[t];
    int p0 = atomicAdd(&g_cursor[r.x], 1);
    int p1 = atomicAdd(&g_cursor[r.y], 1);
    int p2 = atomicAdd(&g_cursor[r.z], 1);
    int p3 = atomicAdd(&g_cursor[r.w], 1);
    g_sorted_cv[p0] = make_int2(c.x, __float_as_int(v.x));
    g_sorted_cv[p1] = make_int2(c.y, __float_as_int(v.y));
    g_sorted_cv[p2] = make_int2(c.z, __float_as_int(v.z));
    g_sorted_cv[p3] = make_int2(c.w, __float_as_int(v.w));
}

// ---------------- 3) Aggregate: one warp per row, fp16 gather ------------
__global__ __launch_bounds__(256)
void aggregate_kernel(const float* __restrict__ bias, float* __restrict__ out) {
    int w    = (blockIdx.x * blockDim.x + threadIdx.x) >> 5;   // row id
    int lane = threadIdx.x & 31;
    if (w >= N_NODES) return;

    int s = g_rowptr[w];
    int e = g_rowptr[w + 1];

    // lane covers cols lane*4 .. lane*4+3  (uint2 = 4 halves per edge)
    float4 acc = make_float4(0.f, 0.f, 0.f, 0.f);
    int j = s;
    for (; j + 3 < e; j += 4) {
        int2 cv0 = g_sorted_cv[j];
        int2 cv1 = g_sorted_cv[j + 1];
        int2 cv2 = g_sorted_cv[j + 2];
        int2 cv3 = g_sorted_cv[j + 3];
        uint2 s0 = *(const uint2*)&g_support_h[(size_t)cv0.x * 64 + lane * 2];
        uint2 s1 = *(const uint2*)&g_support_h[(size_t)cv1.x * 64 + lane * 2];
        uint2 s2 = *(const uint2*)&g_support_h[(size_t)cv2.x * 64 + lane * 2];
        uint2 s3 = *(const uint2*)&g_support_h[(size_t)cv3.x * 64 + lane * 2];
        float v0 = __int_as_float(cv0.y), v1 = __int_as_float(cv1.y);
        float v2 = __int_as_float(cv2.y), v3 = __int_as_float(cv3.y);
        {
            float2 a = __half22float2(*(__half2*)&s0.x), b = __half22float2(*(__half2*)&s0.y);
            acc.x += v0 * a.x; acc.y += v0 * a.y; acc.z += v0 * b.x; acc.w += v0 * b.y;
        }
        {
            float2 a = __half22float2(*(__half2*)&s1.x), b = __half22float2(*(__half2*)&s1.y);
            acc.x += v1 * a.x; acc.y += v1 * a.y; acc.z += v1 * b.x; acc.w += v1 * b.y;
        }
        {
            float2 a = __half22float2(*(__half2*)&s2.x), b = __half22float2(*(__half2*)&s2.y);
            acc.x += v2 * a.x; acc.y += v2 * a.y; acc.z += v2 * b.x; acc.w += v2 * b.y;
        }
        {
            float2 a = __half22float2(*(__half2*)&s3.x), b = __half22float2(*(__half2*)&s3.y);
            acc.x += v3 * a.x; acc.y += v3 * a.y; acc.z += v3 * b.x; acc.w += v3 * b.y;
        }
    }
    for (; j < e; j++) {
        int2 cv = g_sorted_cv[j];
        float v = __int_as_float(cv.y);
        uint2 s0 = *(const uint2*)&g_support_h[(size_t)cv.x * 64 + lane * 2];
        float2 a = __half22float2(*(__half2*)&s0.x), b = __half22float2(*(__half2*)&s0.y);
        acc.x += v * a.x; acc.y += v * a.y; acc.z += v * b.x; acc.w += v * b.y;
    }

    float4 bq = ((const float4*)bias)[lane];
    acc.x += bq.x; acc.y += bq.y; acc.z += bq.z; acc.w += bq.w;
    *(float4*)&out[(size_t)w * D_OUT + lane * 4] = acc;
}

// ---------------- launch ------------------------------------------------
extern "C" void kernel_launch(void* const* d_in, const int* in_sizes, int n_in,
                              void* d_out, int out_size) {
    const float* in_feature = (const float*)d_in[0];   // [N, 256]
    const int*   edge_rows  = (const int*)d_in[1];     // [E]
    const int*   edge_cols  = (const int*)d_in[2];     // [E]
    const float* edge_vals  = (const float*)d_in[3];   // [E]
    const float* weight     = (const float*)d_in[4];   // [256, 128]
    const float* bias       = (const float*)d_in[5];   // [128]
    float*       out        = (float*)d_out;           // [N, 128]

    (void)in_sizes; (void)n_in; (void)out_size;

    static cudaStream_t s2 = 0;
    static cudaEvent_t ev_fork = 0, ev_join = 0;
    static void* counts_ptr = 0;
    static int init_done = 0;
    if (!init_done) {
        cudaFuncSetAttribute(gemm_mma_kernel, cudaFuncAttributeMaxDynamicSharedMemorySize, SM_TOTAL_B);
        cudaStreamCreateWithFlags(&s2, cudaStreamNonBlocking);
        cudaEventCreateWithFlags(&ev_fork, cudaEventDisableTiming);
        cudaEventCreateWithFlags(&ev_join, cudaEventDisableTiming);
        cudaGetSymbolAddress(&counts_ptr, g_counts);
        init_done = 1;
    }

    // fork: CSR build runs concurrently with the GEMM path
    cudaEventRecord(ev_fork, 0);
    cudaStreamWaitEvent(s2, ev_fork, 0);

    // --- main stream: W split + GEMM (tensor pipe / DRAM-bound) ---
    wprep_kernel<<<(D_IN * D_OUT + 255) / 256, 256>>>(weight);
    gemm_mma_kernel<<<148, 256, SM_TOTAL_B>>>(in_feature);

    // --- s2: CSR build (L2-atomic-bound) ---
    cudaMemsetAsync(counts_ptr, 0, N_NODES * sizeof(int), s2);
    hist4_kernel<<<(N_EDGES / 4 + 255) / 256, 256, 0, s2>>>(edge_rows);
    scan1_kernel<<<NSB, SCAN_B, 0, s2>>>();
    scan2_kernel<<<1, 128, 0, s2>>>();
    scan3_kernel<<<(N_NODES + 255) / 256, 256, 0, s2>>>();
    scatter4_kernel<<<(N_EDGES / 4 + 255) / 256, 256, 0, s2>>>(edge_rows, edge_cols, edge_vals);

    // join
    cudaEventRecord(ev_join, s2);
    cudaStreamWaitEvent(0, ev_join, 0);

    // 3) out = A @ support + bias   (one warp per row)
    int blocks = (N_NODES * 32 + 255) / 256;
    aggregate_kernel<<<blocks, 256>>>(bias, out);
}

// round 6
// speedup vs baseline: 1.7859x; 1.0700x over previous
#include <cuda_runtime.h>
#include <cuda_bf16.h>
#include <cuda_fp16.h>
#include <stdint.h>

#define N_NODES 100000
#define N_EDGES 1600000
#define D_IN    256
#define D_OUT   128
#define N_TILES ((N_NODES + 127) / 128)   // 782

// ---------------- device scratch (no allocations allowed) ----------------
// support stored as fp16, packed half2 in u32: [N_NODES][64] u32
__device__ uint32_t g_support_h[(size_t)N_NODES * (D_OUT / 2)];   // 25.6 MB
__device__ int   g_counts[N_NODES];
__device__ int   g_rowptr[N_NODES + 1];
__device__ int   g_cursor[N_NODES];
__device__ int2  g_sorted_cv[N_EDGES];                 // (col, val-bits) sorted by row

// W split into bf16 hi/lo, K-major-pair padded layout: u32[n*132 + k/2]
#define WSTRIDE 132
__device__ uint32_t g_w_hi[128 * WSTRIDE];
__device__ uint32_t g_w_lo[128 * WSTRIDE];

#define SCAN_B 1024
#define NSB    ((N_NODES + SCAN_B - 1) / SCAN_B)       // 98
__device__ int   g_blocksums[NSB];

// ---------------- 0) W prep: split fp32 W -> bf16 hi/lo ------------------
__global__ void wprep_kernel(const float* __restrict__ W) {
    int idx = blockIdx.x * blockDim.x + threadIdx.x;   // 0..32767
    if (idx >= D_IN * D_OUT) return;
    int n = idx & 127;          // output col
    int k = idx >> 7;           // input dim (K)
    float w = W[(size_t)k * D_OUT + n];
    __nv_bfloat16 hb = __float2bfloat16(w);
    float hf = __bfloat162float(hb);
    __nv_bfloat16 lb = __float2bfloat16(w - hf);
    int u = n * WSTRIDE + (k >> 1);
    int h = k & 1;
    ((uint16_t*)&g_w_hi[u])[h] = *(uint16_t*)&hb;
    ((uint16_t*)&g_w_lo[u])[h] = *(uint16_t*)&lb;
}

// ---------------- 1) HMMA GEMM: support = X @ W (fp16 output) ------------
#define ASTRIDE 20
#define W_U32   (128 * WSTRIDE)
#define A_U32   (128 * ASTRIDE)
#define SM_TOTAL_B ((2 * W_U32 + 4 * A_U32) * 4)   // 176128 bytes

// pack two fp32 -> bf16x2 (f0 low half, f1 high half)
__device__ __forceinline__ uint32_t pack_bf(float f0, float f1) {
    uint32_t r;
    asm("cvt.rn.bf16x2.f32 %0, %1, %2;" : "=r"(r) : "f"(f1), "f"(f0));
    return r;
}

__device__ __forceinline__ void mma16816(float* d, const uint32_t* a, const uint32_t* b) {
    asm volatile(
        "mma.sync.aligned.m16n8k16.row.col.f32.bf16.bf16.f32 "
        "{%0,%1,%2,%3}, {%4,%5,%6,%7}, {%8,%9}, {%0,%1,%2,%3};"
        : "+f"(d[0]), "+f"(d[1]), "+f"(d[2]), "+f"(d[3])
        : "r"(a[0]), "r"(a[1]), "r"(a[2]), "r"(a[3]), "r"(b[0]), "r"(b[1]));
}

__global__ __launch_bounds__(256, 1)
void gemm_mma_kernel(const float* __restrict__ A) {
    extern __shared__ uint32_t smem[];
    uint32_t* w_hi  = smem;
    uint32_t* w_lo  = smem + W_U32;
    uint32_t* a_buf = smem + 2 * W_U32;   // [stage][term][A_U32]

    const int tid    = threadIdx.x;
    const int wid    = tid >> 5;
    const int lane   = tid & 31;
    const int warp_m = wid & 3;           // 4 row-bands of 32
    const int warp_n = wid >> 2;          // 2 col-bands of 64
    const int g      = lane >> 2;         // groupID
    const int c      = lane & 3;          // threadID_in_group

    // W hi/lo resident in SMEM (read once from gmem per CTA)
    for (int i = tid; i < W_U32; i += 256) { w_hi[i] = g_w_hi[i]; w_lo[i] = g_w_lo[i]; }
    __syncthreads();

    const int a_row  = tid >> 1;          // 0..127
    const int a_half = tid & 1;           // which 16-float half of the 32-k block

    // ---- register prefetch of the A block (software pipeline) ----
    float4 p0, p1, p2, p3;
    {
        const int gr = blockIdx.x * 128 + a_row;
        if (blockIdx.x < N_TILES && gr < N_NODES) {
            const float4* p = (const float4*)(A + (size_t)gr * D_IN + a_half * 16);
            p0 = p[0]; p1 = p[1]; p2 = p[2]; p3 = p[3];
        } else {
            p0 = p1 = p2 = p3 = make_float4(0.f, 0.f, 0.f, 0.f);
        }
    }

    for (int tile = blockIdx.x; tile < N_TILES; tile += gridDim.x) {
        const int m0 = tile * 128;

        float acc[2][8][4];
#pragma unroll
        for (int mt = 0; mt < 2; mt++)
#pragma unroll
            for (int nt = 0; nt < 8; nt++)
#pragma unroll
                for (int q = 0; q < 4; q++) acc[mt][nt][q] = 0.f;

        for (int kb = 0; kb < 8; kb++) {           // K blocks of 32
            const int stage = kb & 1;
            uint32_t* abh = a_buf + (stage * 2 + 0) * A_U32;
            uint32_t* abl = a_buf + (stage * 2 + 1) * A_U32;

            // ---- convert prefetched regs + store to smem stage ----
            {
                float f[16] = {p0.x, p0.y, p0.z, p0.w, p1.x, p1.y, p1.z, p1.w,
                               p2.x, p2.y, p2.z, p2.w, p3.x, p3.y, p3.z, p3.w};
                uint32_t hi[8], lo[8];
#pragma unroll
                for (int q = 0; q < 8; q++) {
                    uint32_t hq = pack_bf(f[2 * q], f[2 * q + 1]);
                    float h0 = __uint_as_float(hq << 16);
                    float h1 = __uint_as_float(hq & 0xFFFF0000u);
                    hi[q] = hq;
                    lo[q] = pack_bf(f[2 * q] - h0, f[2 * q + 1] - h1);
                }
                uint32_t* dh = abh + a_row * ASTRIDE + a_half * 8;
                uint32_t* dl = abl + a_row * ASTRIDE + a_half * 8;
                *(uint4*)(dh + 0) = make_uint4(hi[0], hi[1], hi[2], hi[3]);
                *(uint4*)(dh + 4) = make_uint4(hi[4], hi[5], hi[6], hi[7]);
                *(uint4*)(dl + 0) = make_uint4(lo[0], lo[1], lo[2], lo[3]);
                *(uint4*)(dl + 4) = make_uint4(lo[4], lo[5], lo[6], lo[7]);
            }

            // ---- issue prefetch for next k-block (or next tile) ----
            {
                int nkb = kb + 1, ntile = tile;
                if (nkb == 8) { nkb = 0; ntile = tile + gridDim.x; }
                const int gr = ntile * 128 + a_row;
                if (ntile < N_TILES && gr < N_NODES) {
                    const float4* p = (const float4*)(A + (size_t)gr * D_IN + nkb * 32 + a_half * 16);
                    p0 = p[0]; p1 = p[1]; p2 = p[2]; p3 = p[3];
                } else {
                    p0 = p1 = p2 = p3 = make_float4(0.f, 0.f, 0.f, 0.f);
                }
            }
            __syncthreads();

            // ---- compute: 2 k16 steps ----
#pragma unroll
            for (int kk = 0; kk < 2; kk++) {
                const int kpl = kk * 8 + c;                 // local kpair for A
                const int kpg = kb * 16 + kk * 8 + c;       // global kpair for W

                uint32_t ah[2][4], al[2][4];
#pragma unroll
                for (int mt = 0; mt < 2; mt++) {
                    const int r0 = (warp_m * 32 + mt * 16 + g) * ASTRIDE;
                    const int r1 = r0 + 8 * ASTRIDE;
                    ah[mt][0] = abh[r0 + kpl];     ah[mt][1] = abh[r1 + kpl];
                    ah[mt][2] = abh[r0 + kpl + 4]; ah[mt][3] = abh[r1 + kpl + 4];
                    al[mt][0] = abl[r0 + kpl];     al[mt][1] = abl[r1 + kpl];
                    al[mt][2] = abl[r0 + kpl + 4]; al[mt][3] = abl[r1 + kpl + 4];
                }
                uint32_t bh[8][2], bl[8][2];
#pragma unroll
                for (int nt = 0; nt < 8; nt++) {
                    const int n = warp_n * 64 + nt * 8 + g;
                    bh[nt][0] = w_hi[n * WSTRIDE + kpg];
                    bh[nt][1] = w_hi[n * WSTRIDE + kpg + 4];
                    bl[nt][0] = w_lo[n * WSTRIDE + kpg];
                    bl[nt][1] = w_lo[n * WSTRIDE + kpg + 4];
                }
#pragma unroll
                for (int mt = 0; mt < 2; mt++)
#pragma unroll
                    for (int nt = 0; nt < 8; nt++) {
                        mma16816(acc[mt][nt], ah[mt], bh[nt]);
                        mma16816(acc[mt][nt], al[mt], bh[nt]);
                        mma16816(acc[mt][nt], ah[mt], bl[nt]);
                    }
            }
        }

        // ---- epilogue: convert to fp16 (half2 per u32) ----
#pragma unroll
        for (int mt = 0; mt < 2; mt++) {
            const int r0 = m0 + warp_m * 32 + mt * 16 + g;
#pragma unroll
            for (int nt = 0; nt < 8; nt++) {
                const int u = warp_n * 32 + nt * 4 + c;     // u32 col index
                if (r0 < N_NODES) {
                    __half2 h = __floats2half2_rn(acc[mt][nt][0], acc[mt][nt][1]);
                    g_support_h[(size_t)r0 * (D_OUT / 2) + u] = *(uint32_t*)&h;
                }
                if (r0 + 8 < N_NODES) {
                    __half2 h = __floats2half2_rn(acc[mt][nt][2], acc[mt][nt][3]);
                    g_support_h[(size_t)(r0 + 8) * (D_OUT / 2) + u] = *(uint32_t*)&h;
                }
            }
        }
        __syncthreads();
    }
}

// ---------------- 2) CSR build: histogram -> scan -> scatter -------------
__global__ void hist4_kernel(const int* __restrict__ rows) {
    int t = blockIdx.x * blockDim.x + threadIdx.x;
    if (t * 4 >= N_EDGES) return;
    int4 r = ((const int4*)rows)[t];
    atomicAdd(&g_counts[r.x], 1);
    atomicAdd(&g_counts[r.y], 1);
    atomicAdd(&g_counts[r.z], 1);
    atomicAdd(&g_counts[r.w], 1);
}

__global__ __launch_bounds__(SCAN_B)
void scan1_kernel() {
    __shared__ int sh[SCAN_B];
    int i = blockIdx.x * SCAN_B + threadIdx.x;
    int v = (i < N_NODES) ? g_counts[i] : 0;
    sh[threadIdx.x] = v;
    __syncthreads();
#pragma unroll
    for (int off = 1; off < SCAN_B; off <<= 1) {
        int t = (threadIdx.x >= off) ? sh[threadIdx.x - off] : 0;
        __syncthreads();
        sh[threadIdx.x] += t;
        __syncthreads();
    }
    if (i < N_NODES) g_rowptr[i] = sh[threadIdx.x] - v;   // block-local exclusive
    if (threadIdx.x == SCAN_B - 1) g_blocksums[blockIdx.x] = sh[SCAN_B - 1];
}

__global__ __launch_bounds__(128)
void scan2_kernel() {    // parallel exclusive scan of the 98 block sums
    __shared__ int sh[128];
    int t = threadIdx.x;
    int v = (t < NSB) ? g_blocksums[t] : 0;
    sh[t] = v;
    __syncthreads();
#pragma unroll
    for (int off = 1; off < 128; off <<= 1) {
        int x = (t >= off) ? sh[t - off] : 0;
        __syncthreads();
        sh[t] += x;
        __syncthreads();
    }
    if (t < NSB) g_blocksums[t] = sh[t] - v;
}

__global__ void scan3_kernel() {
    int i = blockIdx.x * blockDim.x + threadIdx.x;
    if (i < N_NODES) {
        int v = g_rowptr[i] + g_blocksums[i / SCAN_B];
        g_rowptr[i] = v;
        g_cursor[i] = v;
    }
    if (i == 0) g_rowptr[N_NODES] = N_EDGES;
}

__global__ void scatter4_kernel(const int* __restrict__ rows,
                                const int* __restrict__ cols,
                                const float* __restrict__ vals) {
    int t = blockIdx.x * blockDim.x + threadIdx.x;
    if (t * 4 >= N_EDGES) return;
    int4   r = ((const int4*)rows)[t];
    int4   c = ((const int4*)cols)[t];
    float4 v = ((const float4*)vals)[t];
    int p0 = atomicAdd(&g_cursor[r.x], 1);
    int p1 = atomicAdd(&g_cursor[r.y], 1);
    int p2 = atomicAdd(&g_cursor[r.z], 1);
    int p3 = atomicAdd(&g_cursor[r.w], 1);
    g_sorted_cv[p0] = make_int2(c.x, __float_as_int(v.x));
    g_sorted_cv[p1] = make_int2(c.y, __float_as_int(v.y));
    g_sorted_cv[p2] = make_int2(c.z, __float_as_int(v.z));
    g_sorted_cv[p3] = make_int2(c.w, __float_as_int(v.w));
}

// ---------------- 3) Aggregate: warp/row, shfl-broadcast edge data -------
__global__ __launch_bounds__(256)
void aggregate_kernel(const float* __restrict__ bias, float* __restrict__ out) {
    int w    = (blockIdx.x * blockDim.x + threadIdx.x) >> 5;   // row id
    int lane = threadIdx.x & 31;
    if (w >= N_NODES) return;

    const int s = g_rowptr[w];
    const int e = g_rowptr[w + 1];

    // lane covers cols lane*4 .. lane*4+3  (uint2 = 4 halves per edge)
    float4 acc = ((const float4*)bias)[lane];

    for (int base = s; base < e; base += 32) {
        const int rem = e - base;
        int2 cv = make_int2(0, 0);
        if (lane < rem) cv = g_sorted_cv[base + lane];    // one coalesced load
        const int n = rem < 32 ? rem : 32;

#pragma unroll 4
        for (int j = 0; j < n; j++) {
            const int   col = __shfl_sync(0xFFFFFFFFu, cv.x, j);
            const float v   = __int_as_float(__shfl_sync(0xFFFFFFFFu, cv.y, j));
            uint2 sv = *(const uint2*)&g_support_h[(size_t)col * 64 + lane * 2];
            float2 a = __half22float2(*(__half2*)&sv.x);
            float2 b = __half22float2(*(__half2*)&sv.y);
            acc.x += v * a.x; acc.y += v * a.y; acc.z += v * b.x; acc.w += v * b.y;
        }
    }

    *(float4*)&out[(size_t)w * D_OUT + lane * 4] = acc;
}

// ---------------- launch ------------------------------------------------
extern "C" void kernel_launch(void* const* d_in, const int* in_sizes, int n_in,
                              void* d_out, int out_size) {
    const float* in_feature = (const float*)d_in[0];   // [N, 256]
    const int*   edge_rows  = (const int*)d_in[1];     // [E]
    const int*   edge_cols  = (const int*)d_in[2];     // [E]
    const float* edge_vals  = (const float*)d_in[3];   // [E]
    const float* weight     = (const float*)d_in[4];   // [256, 128]
    const float* bias       = (const float*)d_in[5];   // [128]
    float*       out        = (float*)d_out;           // [N, 128]

    (void)in_sizes; (void)n_in; (void)out_size;

    static cudaStream_t s2 = 0;
    static cudaEvent_t ev_fork = 0, ev_join = 0;
    static void* counts_ptr = 0;
    static int init_done = 0;
    if (!init_done) {
        cudaFuncSetAttribute(gemm_mma_kernel, cudaFuncAttributeMaxDynamicSharedMemorySize, SM_TOTAL_B);
        cudaStreamCreateWithFlags(&s2, cudaStreamNonBlocking);
        cudaEventCreateWithFlags(&ev_fork, cudaEventDisableTiming);
        cudaEventCreateWithFlags(&ev_join, cudaEventDisableTiming);
        cudaGetSymbolAddress(&counts_ptr, g_counts);
        init_done = 1;
    }

    // fork: CSR build runs concurrently with the GEMM path
    cudaEventRecord(ev_fork, 0);
    cudaStreamWaitEvent(s2, ev_fork, 0);

    // --- main stream: W split + GEMM (tensor pipe / DRAM-bound) ---
    wprep_kernel<<<(D_IN * D_OUT + 255) / 256, 256>>>(weight);
    gemm_mma_kernel<<<148, 256, SM_TOTAL_B>>>(in_feature);

    // --- s2: CSR build (L2-atomic-bound) ---
    cudaMemsetAsync(counts_ptr, 0, N_NODES * sizeof(int), s2);
    hist4_kernel<<<(N_EDGES / 4 + 255) / 256, 256, 0, s2>>>(edge_rows);
    scan1_kernel<<<NSB, SCAN_B, 0, s2>>>();
    scan2_kernel<<<1, 128, 0, s2>>>();
    scan3_kernel<<<(N_NODES + 255) / 256, 256, 0, s2>>>();
    scatter4_kernel<<<(N_EDGES / 4 + 255) / 256, 256, 0, s2>>>(edge_rows, edge_cols, edge_vals);

    // join
    cudaEventRecord(ev_join, s2);
    cudaStreamWaitEvent(0, ev_join, 0);

    // 3) out = A @ support + bias   (one warp per row)
    int blocks = (N_NODES * 32 + 255) / 256;
    aggregate_kernel<<<blocks, 256>>>(bias, out);
}